// round 3
// baseline (speedup 1.0000x reference)
#include <cuda_runtime.h>

// out[b, p] = s[b, ROW[p]] * s[b, COL[p]],  s[b,f] = sum_e x[b,f,e]
// B=16384, F=32, E=64, P = F*(F-1)/2 = 496.
//
// One CTA per batch row. 512 threads, each loads one float4 (batch row =
// 2048 floats = 512 float4, fully coalesced). 16 consecutive threads own one
// field (16 float4 = 64 floats); butterfly shfl reduce within the 16-lane
// group, leader stores the field sum to smem. Then threads 0..495 compute
// their (i,j) pair index analytically and write the product.

static constexpr int BATCH  = 16384;
static constexpr int FIELDS = 32;
static constexpr int EMBED  = 64;
static constexpr int PAIRS  = 496;          // 32*31/2
static constexpr int ROW_F4 = FIELDS * EMBED / 4;   // 512 float4 per batch

__global__ __launch_bounds__(512, 4)
void opn_kernel(const float* __restrict__ x, float* __restrict__ out) {
    const int b = blockIdx.x;
    const int t = threadIdx.x;          // 0..511

    // ---- load + per-field reduce ----
    const float4* xb = reinterpret_cast<const float4*>(x) + (size_t)b * ROW_F4;
    float4 v = xb[t];
    float s = (v.x + v.y) + (v.z + v.w);

    // reduce across the 16-lane group that owns this field
    s += __shfl_xor_sync(0xffffffffu, s, 1);
    s += __shfl_xor_sync(0xffffffffu, s, 2);
    s += __shfl_xor_sync(0xffffffffu, s, 4);
    s += __shfl_xor_sync(0xffffffffu, s, 8);

    __shared__ float ssum[FIELDS];
    if ((t & 15) == 0) ssum[t >> 4] = s;
    __syncthreads();

    // ---- pairwise products ----
    if (t < PAIRS) {
        // pair index p = t. offset(i) = i*(63-i)/2 ; find i with
        // offset(i) <= p < offset(i+1), then j = p - offset(i) + i + 1.
        int p = t;
        int i = (int)((63.0f - sqrtf(3969.0f - 8.0f * (float)p)) * 0.5f);
        if (i < 0) i = 0;
        if (i > 30) i = 30;
        // fixup for float rounding (at most one step)
        while (i > 0 && (i * (63 - i)) / 2 > p) --i;
        while (((i + 1) * (62 - i)) / 2 <= p) ++i;
        int j = p - (i * (63 - i)) / 2 + i + 1;

        out[(size_t)b * PAIRS + p] = ssum[i] * ssum[j];
    }
}

extern "C" void kernel_launch(void* const* d_in, const int* in_sizes, int n_in,
                              void* d_out, int out_size) {
    const float* x = (const float*)d_in[0];
    float* out = (float*)d_out;
    opn_kernel<<<BATCH, 512>>>(x, out);
}

// round 5
// speedup vs baseline: 1.3786x; 1.3786x over previous
#include <cuda_runtime.h>

// out[b, p] = s[b, ROW[p]] * s[b, COL[p]],  s[b,f] = sum_e x[b,f,e]
// B=16384, F=32, E=64, P = 496.
//
// CTA = 256 threads = 8 batches x 32 fields. Each thread reduces one whole
// field (16 float4, fully unrolled -> MLP=16, no shuffles), stores the field
// sum to smem, then the CTA computes 8*496 pairwise products. Pair indices
// (i,j) are derived from the flat index p via closed form, once per thread
// slot, reused across all 8 batches.

static constexpr int BATCH  = 16384;
static constexpr int FIELDS = 32;
static constexpr int EMBED  = 64;
static constexpr int PAIRS  = 496;
static constexpr int BPC    = 8;                 // batches per CTA
static constexpr int THREADS = BPC * FIELDS;     // 256
static constexpr int F4_PER_FIELD = EMBED / 4;   // 16

__device__ __forceinline__ void pair_from_p(int p, int& i, int& j) {
    // off(i) = i*(63-i)/2 ; find i with off(i) <= p < off(i+1)
    i = (int)((63.0f - sqrtf(3969.0f - 8.0f * (float)p)) * 0.5f);
    if (i < 0) i = 0;
    if (i > 30) i = 30;
    while (i > 0 && (i * (63 - i)) / 2 > p) --i;
    while (((i + 1) * (62 - i)) / 2 <= p) ++i;
    j = p - (i * (63 - i)) / 2 + i + 1;
}

__global__ __launch_bounds__(THREADS, 8)
void opn_kernel(const float* __restrict__ x, float* __restrict__ out) {
    const int t  = threadIdx.x;      // 0..255
    const int bl = t >> 5;           // local batch 0..7
    const int f  = t & 31;           // field 0..31
    const int b0 = blockIdx.x * BPC;

    // ---- load one full field (64 floats) and reduce in registers ----
    const float4* xf = reinterpret_cast<const float4*>(x)
                     + ((size_t)(b0 + bl) * FIELDS + f) * F4_PER_FIELD;

    float4 v[F4_PER_FIELD];
    #pragma unroll
    for (int i = 0; i < F4_PER_FIELD; ++i) v[i] = xf[i];   // 16 outstanding LDG.128

    float a0 = 0.f, a1 = 0.f, a2 = 0.f, a3 = 0.f;
    #pragma unroll
    for (int i = 0; i < F4_PER_FIELD; ++i) {
        a0 += v[i].x; a1 += v[i].y; a2 += v[i].z; a3 += v[i].w;
    }
    float s = (a0 + a1) + (a2 + a3);

    __shared__ float ssum[BPC][FIELDS];
    ssum[bl][f] = s;
    __syncthreads();

    // ---- pairwise products: 8*496 outputs, 256 threads ----
    // slot 0: p = t (all threads); slot 1: p = t + 256 (threads with p < 496)
    int i0, j0;
    pair_from_p(t, i0, j0);

    int p1 = t + THREADS;
    int i1 = 0, j1 = 1;
    bool has1 = (p1 < PAIRS);
    if (has1) pair_from_p(p1, i1, j1);

    #pragma unroll
    for (int b = 0; b < BPC; ++b) {
        float* ob = out + (size_t)(b0 + b) * PAIRS;
        ob[t] = ssum[b][i0] * ssum[b][j0];
        if (has1) ob[p1] = ssum[b][i1] * ssum[b][j1];
    }
}

extern "C" void kernel_launch(void* const* d_in, const int* in_sizes, int n_in,
                              void* d_out, int out_size) {
    const float* x = (const float*)d_in[0];
    float* out = (float*)d_out;
    opn_kernel<<<BATCH / BPC, THREADS>>>(x, out);
}

// round 6
// speedup vs baseline: 1.5371x; 1.1150x over previous
#include <cuda_runtime.h>

// out[b, p] = s[b, ROW[p]] * s[b, COL[p]],  s[b,f] = sum_e x[b,f,e]
// B=16384, F=32, E=64, P = 496.
//
// One warp per batch, 8 warps (8 batches) per CTA. Each thread loads 16
// float4 fully coalesced (warp covers the 8KB batch row). Per chunk k the
// warp holds 2 fields (16 lanes each); reduce float4->scalar then 4-step
// shfl_xor within the 16-lane group. Leaders scatter the 32 field sums to
// smem; then the warp computes all 496 pairwise products for its batch.
// Warps are fully independent: no __syncthreads.

static constexpr int BATCH  = 16384;
static constexpr int FIELDS = 32;
static constexpr int PAIRS  = 496;
static constexpr int WPC    = 8;                // warps (=batches) per CTA
static constexpr int THREADS = WPC * 32;        // 256
static constexpr int F4_PER_BATCH = 512;        // 32 fields * 16 float4

__device__ __forceinline__ void pair_from_p(int p, int& i, int& j) {
    // off(i) = i*(63-i)/2 ; find i with off(i) <= p < off(i+1)
    i = (int)((63.0f - sqrtf(3969.0f - 8.0f * (float)p)) * 0.5f);
    if (i < 0) i = 0;
    if (i > 30) i = 30;
    while (i > 0 && (i * (63 - i)) / 2 > p) --i;
    while (((i + 1) * (62 - i)) / 2 <= p) ++i;
    j = p - (i * (63 - i)) / 2 + i + 1;
}

__global__ __launch_bounds__(THREADS, 6)
void opn_kernel(const float* __restrict__ x, float* __restrict__ out) {
    const int w    = threadIdx.x >> 5;
    const int lane = threadIdx.x & 31;
    const int b    = blockIdx.x * WPC + w;

    const float4* xb = reinterpret_cast<const float4*>(x)
                     + (size_t)b * F4_PER_BATCH;

    __shared__ float ssum[WPC][FIELDS];

    // ---- coalesced load + per-field reduce (16 independent chains) ----
    #pragma unroll
    for (int k = 0; k < 16; ++k) {
        float4 v = xb[k * 32 + lane];               // 1 wavefront per LDG.128
        float s = (v.x + v.y) + (v.z + v.w);
        // sum the 16 lanes that share this field
        s += __shfl_xor_sync(0xffffffffu, s, 1);
        s += __shfl_xor_sync(0xffffffffu, s, 2);
        s += __shfl_xor_sync(0xffffffffu, s, 4);
        s += __shfl_xor_sync(0xffffffffu, s, 8);
        if ((lane & 15) == 0)
            ssum[w][2 * k + (lane >> 4)] = s;       // lanes 0 and 16 lead
    }
    __syncwarp();

    // ---- 496 pairwise products for this warp's batch ----
    float* ob = out + (size_t)b * PAIRS;
    #pragma unroll
    for (int k = 0; k < 16; ++k) {
        int p = k * 32 + lane;
        if (p < PAIRS) {
            int i, j;
            pair_from_p(p, i, j);
            ob[p] = ssum[w][i] * ssum[w][j];        // 128B-coalesced stores
        }
    }
}

extern "C" void kernel_launch(void* const* d_in, const int* in_sizes, int n_in,
                              void* d_out, int out_size) {
    const float* x = (const float*)d_in[0];
    float* out = (float*)d_out;
    opn_kernel<<<BATCH / WPC, THREADS>>>(x, out);
}

// round 8
// speedup vs baseline: 1.7246x; 1.1220x over previous
#include <cuda_runtime.h>

// out[b, p] = s[b, ROW[p]] * s[b, COL[p]],  s[b,f] = sum_e x[b,f,e]
// B=16384, F=32, E=64, P = 496.
//
// One warp per batch, 8 warps/CTA. Per warp:
//   phase A: 16 coalesced float4 loads, horizontal-reduce each to a scalar,
//            store to stride-33 padded smem (conflict-free STS).
//   phase B: lane f reads the 16 partials of field f (contiguous, padded ->
//            conflict-free LDS), adds -> ssum[w][f].
//   phase C: 4x STG.128, 4 pairs each, (i,j) from a CTA-wide packed table
//            built once at kernel start (one __syncthreads; warps are
//            independent afterward).

static constexpr int BATCH   = 16384;
static constexpr int FIELDS  = 32;
static constexpr int PAIRS_N = 496;
static constexpr int WPC     = 8;            // warps (=batches) per CTA
static constexpr int THREADS = WPC * 32;     // 256
static constexpr int F4B     = 512;          // float4 per batch row
static constexpr int PSTRIDE = 33;           // padded row for conflict-free transpose

__global__ __launch_bounds__(THREADS, 6)
void opn_kernel(const float* __restrict__ x, float* __restrict__ out) {
    __shared__ unsigned short tab[512];              // packed (i | j<<8), 496 used
    __shared__ float part[WPC][16 * PSTRIDE];        // per-warp transpose buffer
    __shared__ float ssum[WPC][FIELDS];

    const int t    = threadIdx.x;
    const int w    = t >> 5;
    const int lane = t & 31;
    const int b    = blockIdx.x * WPC + w;

    // ---- build pair table: thread t computes entries 2t, 2t+1 ----
    if (t < PAIRS_N / 2) {
        int p = 2 * t;
        int i = (int)((63.0f - sqrtf(3969.0f - 8.0f * (float)p)) * 0.5f);
        if (i < 0) i = 0;
        if (i > 30) i = 30;
        while (i > 0 && (i * (63 - i)) / 2 > p) --i;
        while (((i + 1) * (62 - i)) / 2 <= p) ++i;
        int j = p - (i * (63 - i)) / 2 + i + 1;
        tab[p] = (unsigned short)(i | (j << 8));
        tab[p + 1] = (j < 31) ? (unsigned short)(i | ((j + 1) << 8))
                              : (unsigned short)((i + 1) | ((i + 2) << 8));
    }
    __syncthreads();   // table visible; warps fully independent from here on

    // ---- phase A: coalesced loads + horizontal reduce + transpose store ----
    const float4* xb = reinterpret_cast<const float4*>(x) + (size_t)b * F4B;
    float* pw = part[w];
    #pragma unroll
    for (int k = 0; k < 16; ++k) {
        float4 v = xb[k * 32 + lane];                 // 1 wavefront per LDG.128
        pw[k * PSTRIDE + lane] = (v.x + v.y) + (v.z + v.w);
    }
    __syncwarp();

    // ---- phase B: lane f sums the 16 partials of field f ----
    {
        const float* pr = pw + (lane >> 1) * PSTRIDE + ((lane & 1) << 4);
        float acc = 0.f;
        #pragma unroll
        for (int i = 0; i < 16; ++i) acc += pr[i];
        ssum[w][lane] = acc;
    }
    __syncwarp();

    // ---- phase C: 496 products, 4 per thread per iter, STG.128 ----
    float* ob = out + (size_t)b * PAIRS_N;
    const float* sw = ssum[w];
    #pragma unroll
    for (int m = 0; m < 4; ++m) {
        int p = m * 128 + lane * 4;
        if (p < PAIRS_N) {
            ushort4 e = *reinterpret_cast<const ushort4*>(tab + p);
            float4 r;
            r.x = sw[e.x & 255] * sw[e.x >> 8];
            r.y = sw[e.y & 255] * sw[e.y >> 8];
            r.z = sw[e.z & 255] * sw[e.z >> 8];
            r.w = sw[e.w & 255] * sw[e.w >> 8];
            *reinterpret_cast<float4*>(ob + p) = r;
        }
    }
}

extern "C" void kernel_launch(void* const* d_in, const int* in_sizes, int n_in,
                              void* d_out, int out_size) {
    const float* x = (const float*)d_in[0];
    float* out = (float*)d_out;
    opn_kernel<<<BATCH / WPC, THREADS>>>(x, out);
}

// round 12
// speedup vs baseline: 1.7640x; 1.0229x over previous
#include <cuda_runtime.h>

// out[b, p] = s[b, ROW[p]] * s[b, COL[p]],  s[b,f] = sum_e x[b,f,e]
// B=16384, F=32, E=64, P = 496.
//
// One warp per batch, 8 warps/CTA, forced occ 8 (<=32 regs). Per warp:
//   phase A: 16 coalesced LDG.128 (streaming, __ldcs), horizontal-reduce each
//            to a scalar, store to stride-33 padded smem (conflict-free STS).
//   phase B: lane f sums the 16 partials of field f (conflict-free LDS).
//   phase C: 4x STG.128 (streaming, __stcs), 4 pairs each, indices from a
//            CTA-wide packed table built once at kernel start.

static constexpr int BATCH   = 16384;
static constexpr int FIELDS  = 32;
static constexpr int PAIRS_N = 496;
static constexpr int WPC     = 8;            // warps (=batches) per CTA
static constexpr int THREADS = WPC * 32;     // 256
static constexpr int F4B     = 512;          // float4 per batch row
static constexpr int PSTRIDE = 33;           // padded row, conflict-free transpose

__global__ __launch_bounds__(THREADS, 8)
void opn_kernel(const float* __restrict__ x, float* __restrict__ out) {
    __shared__ unsigned short tab[512];              // packed (i | j<<8), 496 used
    __shared__ float part[WPC][16 * PSTRIDE];        // per-warp transpose buffer
    __shared__ float ssum[WPC][FIELDS];

    const int t    = threadIdx.x;
    const int w    = t >> 5;
    const int lane = t & 31;
    const int b    = blockIdx.x * WPC + w;

    // ---- build pair table: thread t computes entries 2t, 2t+1 ----
    if (t < PAIRS_N / 2) {
        int p = 2 * t;
        int i = (int)((63.0f - sqrtf(3969.0f - 8.0f * (float)p)) * 0.5f);
        if (i < 0) i = 0;
        if (i > 30) i = 30;
        while (i > 0 && (i * (63 - i)) / 2 > p) --i;
        while (((i + 1) * (62 - i)) / 2 <= p) ++i;
        int j = p - (i * (63 - i)) / 2 + i + 1;
        tab[p] = (unsigned short)(i | (j << 8));
        tab[p + 1] = (j < 31) ? (unsigned short)(i | ((j + 1) << 8))
                              : (unsigned short)((i + 1) | ((i + 2) << 8));
    }
    __syncthreads();   // table visible; warps fully independent from here on

    // ---- phase A: streaming coalesced loads + horizontal reduce + transpose ----
    const float4* xb = reinterpret_cast<const float4*>(x) + (size_t)b * F4B;
    float* pw = part[w];
    #pragma unroll
    for (int k = 0; k < 16; ++k) {
        float4 v = __ldcs(&xb[k * 32 + lane]);        // LDG.128.CS, 1 wf per inst
        pw[k * PSTRIDE + lane] = (v.x + v.y) + (v.z + v.w);
    }
    __syncwarp();

    // ---- phase B: lane f sums the 16 partials of field f ----
    {
        const float* pr = pw + (lane >> 1) * PSTRIDE + ((lane & 1) << 4);
        float acc = 0.f;
        #pragma unroll
        for (int i = 0; i < 16; ++i) acc += pr[i];
        ssum[w][lane] = acc;
    }
    __syncwarp();

    // ---- phase C: 496 products, 4 per thread per iter, streaming STG.128 ----
    float* ob = out + (size_t)b * PAIRS_N;
    const float* sw = ssum[w];
    #pragma unroll
    for (int m = 0; m < 4; ++m) {
        int p = m * 128 + lane * 4;
        if (p < PAIRS_N) {
            ushort4 e = *reinterpret_cast<const ushort4*>(tab + p);
            float4 r;
            r.x = sw[e.x & 255] * sw[e.x >> 8];
            r.y = sw[e.y & 255] * sw[e.y >> 8];
            r.z = sw[e.z & 255] * sw[e.z >> 8];
            r.w = sw[e.w & 255] * sw[e.w >> 8];
            __stcs(reinterpret_cast<float4*>(ob + p), r);
        }
    }
}

extern "C" void kernel_launch(void* const* d_in, const int* in_sizes, int n_in,
                              void* d_out, int out_size) {
    const float* x = (const float*)d_in[0];
    float* out = (float*)d_out;
    opn_kernel<<<BATCH / WPC, THREADS>>>(x, out);
}

// round 13
// speedup vs baseline: 1.8607x; 1.0548x over previous
#include <cuda_runtime.h>

// out[b, p] = s[b, ROW[p]] * s[b, COL[p]],  s[b,f] = sum_e x[b,f,e]
// B=16384, F=32, E=64, P = 496.
//
// One warp handles NB=2 batches (loop); 8 warps/CTA; grid = 1024 CTAs so the
// whole launch fits in ONE wave at occ 8 (148*8 = 1184 >= 1024), eliminating
// the partial second wave of the previous version. Per warp per batch:
//   A: 16 coalesced LDG.128.CS, horizontal-reduce to scalar, STS to a
//      stride-33 padded tile (conflict-free).
//   B: lane f sums the 16 partials of field f (conflict-free LDS).
//   C: 4x STG.128.CS, 4 pairs each, indices from a packed table built once.

static constexpr int BATCH   = 16384;
static constexpr int FIELDS  = 32;
static constexpr int PAIRS_N = 496;
static constexpr int WPC     = 8;            // warps per CTA
static constexpr int NB      = 2;            // batches per warp
static constexpr int THREADS = WPC * 32;     // 256
static constexpr int F4B     = 512;          // float4 per batch row
static constexpr int PSTRIDE = 33;           // padded row, conflict-free transpose
static constexpr int GRID    = BATCH / (WPC * NB);   // 1024 -> single wave

__global__ __launch_bounds__(THREADS, 8)
void opn_kernel(const float* __restrict__ x, float* __restrict__ out) {
    __shared__ unsigned short tab[512];              // packed (i | j<<8), 496 used
    __shared__ float part[WPC][16 * PSTRIDE];        // per-warp transpose buffer
    __shared__ float ssum[WPC][FIELDS];

    const int t    = threadIdx.x;
    const int w    = t >> 5;
    const int lane = t & 31;

    // ---- build pair table: thread t computes entries 2t, 2t+1 ----
    if (t < PAIRS_N / 2) {
        int p = 2 * t;
        int i = (int)((63.0f - sqrtf(3969.0f - 8.0f * (float)p)) * 0.5f);
        if (i < 0) i = 0;
        if (i > 30) i = 30;
        while (i > 0 && (i * (63 - i)) / 2 > p) --i;
        while (((i + 1) * (62 - i)) / 2 <= p) ++i;
        int j = p - (i * (63 - i)) / 2 + i + 1;
        tab[p] = (unsigned short)(i | (j << 8));
        tab[p + 1] = (j < 31) ? (unsigned short)(i | ((j + 1) << 8))
                              : (unsigned short)((i + 1) | ((i + 2) << 8));
    }
    __syncthreads();   // table visible; warps fully independent from here on

    float* pw = part[w];
    float* sw = ssum[w];

    #pragma unroll
    for (int n = 0; n < NB; ++n) {
        const int b = (blockIdx.x * WPC + w) * NB + n;

        // ---- A: streaming coalesced loads + horizontal reduce + transpose ----
        const float4* xb = reinterpret_cast<const float4*>(x) + (size_t)b * F4B;
        #pragma unroll
        for (int k = 0; k < 16; ++k) {
            float4 v = __ldcs(&xb[k * 32 + lane]);    // LDG.128.CS, 1 wf per inst
            pw[k * PSTRIDE + lane] = (v.x + v.y) + (v.z + v.w);
        }
        __syncwarp();

        // ---- B: lane f sums the 16 partials of field f ----
        {
            const float* pr = pw + (lane >> 1) * PSTRIDE + ((lane & 1) << 4);
            float acc = 0.f;
            #pragma unroll
            for (int i = 0; i < 16; ++i) acc += pr[i];
            sw[lane] = acc;
        }
        __syncwarp();

        // ---- C: 496 products, 4 per thread per iter, streaming STG.128 ----
        float* ob = out + (size_t)b * PAIRS_N;
        #pragma unroll
        for (int m = 0; m < 4; ++m) {
            int p = m * 128 + lane * 4;
            if (p < PAIRS_N) {
                ushort4 e = *reinterpret_cast<const ushort4*>(tab + p);
                float4 r;
                r.x = sw[e.x & 255] * sw[e.x >> 8];
                r.y = sw[e.y & 255] * sw[e.y >> 8];
                r.z = sw[e.z & 255] * sw[e.z >> 8];
                r.w = sw[e.w & 255] * sw[e.w >> 8];
                __stcs(reinterpret_cast<float4*>(ob + p), r);
            }
        }
        __syncwarp();   // protect part[] WAR before next batch's STS
    }
}

extern "C" void kernel_launch(void* const* d_in, const int* in_sizes, int n_in,
                              void* d_out, int out_size) {
    const float* x = (const float*)d_in[0];
    float* out = (float*)d_out;
    opn_kernel<<<GRID, THREADS>>>(x, out);
}